// round 14
// baseline (speedup 1.0000x reference)
#include <cuda_runtime.h>
#include <cuda_bf16.h>

#define BB 16
#define NN 8192
#define SS 1024
#define KK 32
#define FULLMASK 0xFFFFFFFFu
typedef unsigned long long ull;

// ---------------- scratch (no allocs allowed) ----------------
__device__ float  g_newxyz[BB * SS * 3];   // FPS-selected centers
__device__ float  g_gmax[BB * SS * 3];     // max over K of diff, per coord
__device__ float  g_gsum[BB * SS * 3];     // sum over K of diff, per coord
__device__ double g_acc[2];                // sum(diff), sum(diff^2) for global std
__device__ float  g_lc[BB * 6 * SS];       // pooled features (raw, pre-BN1)
__device__ int    g_prog[BB * 32];         // progress, one 128B line per batch
__device__ double g_ch[12];                // BN1 per-channel sum[6], sumsq[6]
__device__ float  g_tf[BB * 36];           // cdist features pre-BN2
__device__ int    g_done;                  // finalize2 completion counter

// ---------------- f32x2 helpers (Blackwell packed fp32) ----------------
__device__ __forceinline__ ull pk2(float lo, float hi) {
    ull r;
    asm("mov.b64 %0, {%1, %2};" : "=l"(r) : "f"(lo), "f"(hi));
    return r;
}
__device__ __forceinline__ void upk2(float& lo, float& hi, ull v) {
    asm("mov.b64 {%0, %1}, %2;" : "=f"(lo), "=f"(hi) : "l"(v));
}
__device__ __forceinline__ ull add2(ull a, ull b) {
    ull r;
    asm("add.rn.f32x2 %0, %1, %2;" : "=l"(r) : "l"(a), "l"(b));
    return r;
}
__device__ __forceinline__ ull mul2(ull a, ull b) {
    ull r;
    asm("mul.rn.f32x2 %0, %1, %2;" : "=l"(r) : "l"(a), "l"(b));
    return r;
}

// ---------------- release/acquire progress channel ----------------
__device__ __forceinline__ void st_rel_gpu(int* p, int v) {
    asm volatile("st.release.gpu.s32 [%0], %1;" :: "l"(p), "r"(v) : "memory");
}
__device__ __forceinline__ int ld_acq_gpu(const int* p) {
    int v;
    asm volatile("ld.acquire.gpu.s32 %0, [%1];" : "=r"(v) : "l"(p) : "memory");
    return v;
}

// ---------------- top-k machinery (R9, proven) ----------------
__device__ __forceinline__ ull u64min(ull a, ull b) { return a < b ? a : b; }
__device__ __forceinline__ ull u64max(ull a, ull b) { return a < b ? b : a; }
__device__ __forceinline__ ull makekey(float d, int idx) {
    unsigned ub = __float_as_uint(d);
    ub ^= ((unsigned)((int)ub >> 31)) | 0x80000000u;
    return ((ull)ub << 13) | (unsigned)idx;
}
__device__ __forceinline__ float kth2kd(ull kth) {
    unsigned ub = (unsigned)(kth >> 13);
    unsigned db = (ub >> 31) ? (ub ^ 0x80000000u) : ~ub;
    return __uint_as_float(db);
}
__device__ __forceinline__ ull sort32(ull key, int lane)
{
#pragma unroll
    for (int k = 2; k <= 32; k <<= 1) {
#pragma unroll
        for (int j = k >> 1; j > 0; j >>= 1) {
            ull other = __shfl_xor_sync(FULLMASK, key, j);
            bool up = ((lane & k) == 0);
            bool takeMin = (((lane & j) == 0) == up);
            key = takeMin ? u64min(key, other) : u64max(key, other);
        }
    }
    return key;
}
__device__ __forceinline__ ull merge32(ull key, ull buf, int lane)
{
    buf = sort32(buf, lane);
    ull rev = __shfl_sync(FULLMASK, buf, 31 - lane);
    key = u64min(key, rev);
#pragma unroll
    for (int j = 16; j > 0; j >>= 1) {
        ull other = __shfl_xor_sync(FULLMASK, key, j);
        bool takeMin = ((lane & j) == 0);
        key = takeMin ? u64min(key, other) : u64max(key, other);
    }
    return key;
}
__device__ __forceinline__ void push_chunk(ull ck, unsigned m, int lane,
                                           ull& key, float& kd,
                                           ull& buf, int& bcnt)
{
    int cnt = __popc(m);
    int r = lane - bcnt;
    bool take = (r >= 0) && (r < cnt);
    unsigned pos = __fns(m, 0, take ? (r + 1) : 1);
    ull got = __shfl_sync(FULLMASK, ck, pos & 31);
    if (take) buf = got;
    bcnt += cnt;
    if (bcnt >= 32) {
        key = merge32(key, buf, lane);
        ull kth = __shfl_sync(FULLMASK, key, 31);
        kd = kth2kd(kth);
        int left = bcnt - 32;
        buf = ~0ull;
        if (left) {   // re-push overflow candidates (extras are harmless)
            int start = cnt - left;
            bool tk2 = lane < left;
            unsigned pos2 = __fns(m, 0, tk2 ? (start + lane + 1) : 1);
            ull got2 = __shfl_sync(FULLMASK, ck, pos2 & 31);
            if (tk2) buf = got2;
        }
        bcnt = left;
    }
}

// =====================================================================
// Fused producer/consumer kernel (R12 structure — measured best).
// 144 blocks x 1024 threads (all resident in wave 1 -> deadlock-free).
//   blocks 0..15   : FPS for batch b (exact R4 math), publishes
//                    g_prog[b*32] every 16 steps via st.release.gpu.
//   blocks 16..143 : kNN (R9 pairing); warps wait via ld.acquire.gpu
//                    with 2us-backoff polling.
// Results are bit-identical to the sequential version.
// =====================================================================
__global__ void __launch_bounds__(1024) fused_kernel(const float* __restrict__ xyz)
{
    extern __shared__ char dyn_smem[];
    const int t = threadIdx.x;
    const int lane = t & 31, warp = t >> 5;

    if (blockIdx.x < BB) {
        // ---------------- FPS path ----------------
        const int b = blockIdx.x;
        const float* X = xyz + (size_t)b * NN * 3;

        ull px2[4], py2[4], pz2[4];
        float dist[8];
#pragma unroll
        for (int i = 0; i < 4; i++) {
            int p0 = t + 1024 * (2 * i);
            int p1 = t + 1024 * (2 * i + 1);
            px2[i] = pk2(X[p0 * 3 + 0], X[p1 * 3 + 0]);
            py2[i] = pk2(X[p0 * 3 + 1], X[p1 * 3 + 1]);
            pz2[i] = pk2(X[p0 * 3 + 2], X[p1 * 3 + 2]);
            dist[2 * i] = 1e10f;
            dist[2 * i + 1] = 1e10f;
        }

        __shared__ unsigned s_val[2][32];
        __shared__ int      s_idx[2][32];

        float cx = X[0], cy = X[1], cz = X[2];   // sample 0 = point 0
        if (t == 0) {
            float* o = g_newxyz + (size_t)(b * SS) * 3;
            o[0] = cx; o[1] = cy; o[2] = cz;
        }

        for (int s = 0; s < SS - 1; s++) {
            const ull ncx2 = pk2(-cx, -cx);
            const ull ncy2 = pk2(-cy, -cy);
            const ull ncz2 = pk2(-cz, -cz);

            float bestv = -1.0f;
#pragma unroll
            for (int i = 0; i < 4; i++) {
                ull dx2 = add2(px2[i], ncx2);
                ull dy2 = add2(py2[i], ncy2);
                ull dz2 = add2(pz2[i], ncz2);
                ull d2 = add2(add2(mul2(dx2, dx2), mul2(dy2, dy2)), mul2(dz2, dz2));
                float d0, d1;
                upk2(d0, d1, d2);
                float n0 = fminf(dist[2 * i], d0);
                float n1 = fminf(dist[2 * i + 1], d1);
                dist[2 * i] = n0;
                dist[2 * i + 1] = n1;
                bestv = fmaxf(bestv, fmaxf(n0, n1));
            }

            unsigned wm = __reduce_max_sync(FULLMASK, __float_as_uint(bestv));
            float wmf = __uint_as_float(wm);
            // lowest matching index via balanced min-tree (idx monotone in slot)
            unsigned c0 = (dist[0] == wmf) ? (unsigned)(t + (0 << 10)) : 0x7FFFFFFFu;
            unsigned c1 = (dist[1] == wmf) ? (unsigned)(t + (1 << 10)) : 0x7FFFFFFFu;
            unsigned c2_ = (dist[2] == wmf) ? (unsigned)(t + (2 << 10)) : 0x7FFFFFFFu;
            unsigned c3 = (dist[3] == wmf) ? (unsigned)(t + (3 << 10)) : 0x7FFFFFFFu;
            unsigned c4 = (dist[4] == wmf) ? (unsigned)(t + (4 << 10)) : 0x7FFFFFFFu;
            unsigned c5 = (dist[5] == wmf) ? (unsigned)(t + (5 << 10)) : 0x7FFFFFFFu;
            unsigned c6 = (dist[6] == wmf) ? (unsigned)(t + (6 << 10)) : 0x7FFFFFFFu;
            unsigned c7 = (dist[7] == wmf) ? (unsigned)(t + (7 << 10)) : 0x7FFFFFFFu;
            unsigned cand = min(min(min(c0, c1), min(c2_, c3)),
                                min(min(c4, c5), min(c6, c7)));
            cand = __reduce_min_sync(FULLMASK, cand);

            if (lane == 0) { s_val[s & 1][warp] = wm; s_idx[s & 1][warp] = (int)cand; }
            __syncthreads();

            unsigned v = s_val[s & 1][lane];
            int      ci = s_idx[s & 1][lane];
            unsigned gm = __reduce_max_sync(FULLMASK, v);
            unsigned cc = (v == gm) ? (unsigned)ci : 0x7FFFFFFFu;
            int widx = (int)__reduce_min_sync(FULLMASK, cc);

            cx = X[widx * 3 + 0];
            cy = X[widx * 3 + 1];
            cz = X[widx * 3 + 2];
            if (t == 0) {
                float* o = g_newxyz + (size_t)(b * SS + s + 1) * 3;
                o[0] = cx; o[1] = cy; o[2] = cz;
                if ((s & 15) == 15)             // publish progress (release)
                    st_rel_gpu(&g_prog[b * 32], s + 2);
            }
        }
        if (t == 0) st_rel_gpu(&g_prog[b * 32], SS);   // final publish
        return;
    }

    // ---------------- kNN path ----------------
    ulonglong2* sxy = (ulonglong2*)dyn_smem;          // [NN/2] {x2, y2}
    ulonglong2* szw = (ulonglong2*)dyn_smem + NN / 2; // [NN/2] {z2, sq2}
    __shared__ double s_p1[32], s_p2[32];

    const int kb = blockIdx.x - BB;
    const int b  = kb >> 3;                    // 8 blocks per batch
    const int qc = kb & 7;
    const float* X = xyz + (size_t)b * NN * 3;

    for (int j = t; j < NN / 2; j += 1024) {
        const float* p = X + 6 * j;
        float x0 = p[0], y0 = p[1], z0 = p[2];
        float x1 = p[3], y1 = p[4], z1 = p[5];
        float sq0 = __fadd_rn(__fadd_rn(__fmul_rn(x0, x0), __fmul_rn(y0, y0)),
                              __fmul_rn(z0, z0));
        float sq1 = __fadd_rn(__fadd_rn(__fmul_rn(x1, x1), __fmul_rn(y1, y1)),
                              __fmul_rn(z1, z1));
        sxy[j] = make_ulonglong2(pk2(x0, x1), pk2(y0, y1));
        szw[j] = make_ulonglong2(pk2(z0, z1), pk2(sq0, sq1));
    }
    __syncthreads();

    const ull m2two = pk2(-2.0f, -2.0f);
    const int g = qc * 32 + warp;              // 0..255 per batch

    double acc1 = 0.0, acc2 = 0.0;             // meaningful on lane 0 only

    for (int qp = 0; qp < 2; qp++) {
        const int s0 = (qp ? 512 : 0) + 2 * g;
        const int s1 = s0 + 1;

        // wait for fps to publish centroids s0, s1 (acquire; 2us backoff)
        if (ld_acq_gpu(&g_prog[b * 32]) < s1 + 1) {
            do { __nanosleep(2000); } while (ld_acq_gpu(&g_prog[b * 32]) < s1 + 1);
        }

        const float* cen0 = g_newxyz + (size_t)(b * SS + s0) * 3;
        const float* cen1 = g_newxyz + (size_t)(b * SS + s1) * 3;
        const float ax = cen0[0], ay = cen0[1], az = cen0[2];
        const float bx = cen1[0], by = cen1[1], bz = cen1[2];
        const float asq = __fadd_rn(__fadd_rn(__fmul_rn(ax, ax), __fmul_rn(ay, ay)),
                                    __fmul_rn(az, az));
        const float bsq = __fadd_rn(__fadd_rn(__fmul_rn(bx, bx), __fmul_rn(by, by)),
                                    __fmul_rn(bz, bz));
        const ull aX2 = pk2(ax, ax), aY2 = pk2(ay, ay), aZ2 = pk2(az, az);
        const ull aS2 = pk2(asq, asq);
        const ull bX2 = pk2(bx, bx), bY2 = pk2(by, by), bZ2 = pk2(bz, bz);
        const ull bS2 = pk2(bsq, bsq);

        ull key0, key1;
        float kd0, kd1;
        {
            ulonglong2 A = sxy[lane];
            ulonglong2 B = szw[lane];
            ull dot0 = add2(add2(mul2(A.x, aX2), mul2(A.y, aY2)), mul2(B.x, aZ2));
            ull dd0 = add2(add2(mul2(m2two, dot0), aS2), B.y);
            ull dot1 = add2(add2(mul2(A.x, bX2), mul2(A.y, bY2)), mul2(B.x, bZ2));
            ull dd1 = add2(add2(mul2(m2two, dot1), bS2), B.y);
            float de, dq;
            upk2(de, dq, dd0);
            key0 = sort32(makekey(de, 2 * lane), lane);
            key0 = merge32(key0, makekey(dq, 2 * lane + 1), lane);
            kd0 = kth2kd(__shfl_sync(FULLMASK, key0, 31));
            upk2(de, dq, dd1);
            key1 = sort32(makekey(de, 2 * lane), lane);
            key1 = merge32(key1, makekey(dq, 2 * lane + 1), lane);
            kd1 = kth2kd(__shfl_sync(FULLMASK, key1, 31));
        }
        ull buf0 = ~0ull, buf1 = ~0ull;
        int bc0 = 0, bc1 = 0;

        for (int jb = 32; jb < NN / 2; jb += 32) {
            const int j = jb + lane;           // cands 2j, 2j+1
            ulonglong2 A = sxy[j];
            ulonglong2 B = szw[j];
            ull dot0 = add2(add2(mul2(A.x, aX2), mul2(A.y, aY2)), mul2(B.x, aZ2));
            ull dd0 = add2(add2(mul2(m2two, dot0), aS2), B.y);
            ull dot1 = add2(add2(mul2(A.x, bX2), mul2(A.y, bY2)), mul2(B.x, bZ2));
            ull dd1 = add2(add2(mul2(m2two, dot1), bS2), B.y);
            float d0e, d0o, d1e, d1o;
            upk2(d0e, d0o, dd0);
            upk2(d1e, d1o, dd1);
            bool hit = (d0e <= kd0) | (d0o <= kd0) | (d1e <= kd1) | (d1o <= kd1);
            if (__any_sync(FULLMASK, hit)) {
                unsigned m;
                m = __ballot_sync(FULLMASK, d0e <= kd0);
                if (m) push_chunk(makekey(d0e, 2 * j), m, lane, key0, kd0, buf0, bc0);
                m = __ballot_sync(FULLMASK, d0o <= kd0);
                if (m) push_chunk(makekey(d0o, 2 * j + 1), m, lane, key0, kd0, buf0, bc0);
                m = __ballot_sync(FULLMASK, d1e <= kd1);
                if (m) push_chunk(makekey(d1e, 2 * j), m, lane, key1, kd1, buf1, bc1);
                m = __ballot_sync(FULLMASK, d1o <= kd1);
                if (m) push_chunk(makekey(d1o, 2 * j + 1), m, lane, key1, kd1, buf1, bc1);
            }
        }
        if (bc0 > 0) key0 = merge32(key0, buf0, lane);
        if (bc1 > 0) key1 = merge32(key1, buf1, lane);

        // ----- group stats for both queries -----
#pragma unroll
        for (int q = 0; q < 2; q++) {
            ull key = q ? key1 : key0;
            float cx = q ? bx : ax, cy = q ? by : ay, cz = q ? bz : az;
            int sq = q ? s1 : s0;
            int ki = (int)(key & 0x1FFFull);
            ulonglong2 P1 = sxy[ki >> 1];
            ulonglong2 P2 = szw[ki >> 1];
            float xl, xh, yl, yh, zl, zh;
            upk2(xl, xh, P1.x);
            upk2(yl, yh, P1.y);
            upk2(zl, zh, P2.x);
            float px = (ki & 1) ? xh : xl;
            float py = (ki & 1) ? yh : yl;
            float pz = (ki & 1) ? zh : zl;
            float dx = __fsub_rn(px, cx);
            float dy = __fsub_rn(py, cy);
            float dz = __fsub_rn(pz, cz);
            float sdx = dx, sdy = dy, sdz = dz;
            float mdx = dx, mdy = dy, mdz = dz;
            float t1 = dx + dy + dz;
            float t2 = dx * dx + dy * dy + dz * dz;
#pragma unroll
            for (int o = 16; o; o >>= 1) {
                sdx += __shfl_down_sync(FULLMASK, sdx, o);
                sdy += __shfl_down_sync(FULLMASK, sdy, o);
                sdz += __shfl_down_sync(FULLMASK, sdz, o);
                mdx = fmaxf(mdx, __shfl_down_sync(FULLMASK, mdx, o));
                mdy = fmaxf(mdy, __shfl_down_sync(FULLMASK, mdy, o));
                mdz = fmaxf(mdz, __shfl_down_sync(FULLMASK, mdz, o));
                t1 += __shfl_down_sync(FULLMASK, t1, o);
                t2 += __shfl_down_sync(FULLMASK, t2, o);
            }
            if (lane == 0) {
                int ix = (b * SS + sq) * 3;
                g_gsum[ix] = sdx; g_gsum[ix + 1] = sdy; g_gsum[ix + 2] = sdz;
                g_gmax[ix] = mdx; g_gmax[ix + 1] = mdy; g_gmax[ix + 2] = mdz;
                acc1 += (double)t1;
                acc2 += (double)t2;
            }
        }
    }

    if (lane == 0) { s_p1[warp] = acc1; s_p2[warp] = acc2; }
    __syncthreads();
    if (t == 0) {
        double a = 0.0, c = 0.0;
        for (int w = 0; w < 32; w++) { a += s_p1[w]; c += s_p2[w]; }
        atomicAdd(&g_acc[0], a);
        atomicAdd(&g_acc[1], c);
    }
}

// =====================================================================
// K3a: lc build (64 blocks) + BN1 channel sum/sumsq via double atomics.
// =====================================================================
__global__ void __launch_bounds__(256) finalize1_kernel()
{
    const int t = threadIdx.x;
    const int lane = t & 31, warp = t >> 5;
    const int idx = blockIdx.x * 256 + t;     // 0..16383
    __shared__ float s_red[12][8];

    double M = (double)BB * SS * KK * 3;
    double var = (g_acc[1] - g_acc[0] * g_acc[0] / M) / (M - 1.0);  // ddof=1
    const float se = (float)sqrt(var) + 1e-5f;

    int b = idx >> 10, s = idx & (SS - 1);
    const float* gm = g_gmax + idx * 3;
    const float* gs = g_gsum + idx * 3;
    const float* cn = g_newxyz + idx * 3;
    float v[6];
#pragma unroll
    for (int c = 0; c < 3; c++) {
        float mx = __fdiv_rn(gm[c], se);
        float mn = __fdiv_rn(__fdiv_rn(gs[c], 32.0f), se);
        v[c] = __fadd_rn(mx, mn);
        g_lc[(b * 6 + c) * SS + s] = v[c];
    }
#pragma unroll
    for (int c = 0; c < 3; c++) {
        float w = cn[c];
        v[3 + c] = w + w;
        g_lc[(b * 6 + 3 + c) * SS + s] = v[3 + c];
    }

    float sm[12];
#pragma unroll
    for (int c = 0; c < 6; c++) { sm[c] = v[c]; sm[6 + c] = v[c] * v[c]; }
#pragma unroll
    for (int k = 0; k < 12; k++) {
#pragma unroll
        for (int o = 16; o; o >>= 1) sm[k] += __shfl_down_sync(FULLMASK, sm[k], o);
        if (lane == 0) s_red[k][warp] = sm[k];
    }
    __syncthreads();
    if (t < 12) {
        double tot = 0.0;
        for (int w = 0; w < 8; w++) tot += (double)s_red[t][w];
        atomicAdd(&g_ch[t], tot);
    }
}

// =====================================================================
// K3b: cdist with on-the-fly BN1 normalize+relu (16 blocks, one per
// batch); the LAST block to finish also does BN2 + output + resets.
// =====================================================================
__global__ void __launch_bounds__(512) finalize2_kernel(
    const float* __restrict__ bn1g, const float* __restrict__ bn1b,
    const float* __restrict__ bn2g, const float* __restrict__ bn2b,
    float* __restrict__ out)
{
    const int b = blockIdx.x;
    const int t = threadIdx.x, lane = t & 31, warp = t >> 5;
    __shared__ int s_last;
    __shared__ float s_m[36], s_v[36];

    if (t < 6) g_tf[b * 36 + t * 7] = 0.0f;      // diagonal

    if (warp < 15) {
        int i = 0, j = 0, p = warp;
        for (i = 0; i < 5; i++) {
            int row = 5 - i;
            if (p < row) { j = i + 1 + p; break; }
            p -= row;
        }
        const double Ninv = 1.0 / (double)(BB * SS);
        double mid = g_ch[i] * Ninv;
        double vid = g_ch[6 + i] * Ninv - mid * mid;   // biased var
        double mjd = g_ch[j] * Ninv;
        double vjd = g_ch[6 + j] * Ninv - mjd * mjd;
        float mi = (float)mid, di = (float)sqrt(vid + 1e-5);
        float mj = (float)mjd, dj = (float)sqrt(vjd + 1e-5);
        float gi = bn1g[i], bi = bn1b[i];
        float gj = bn1g[j], bj = bn1b[j];

        const float* A  = g_lc + (b * 6 + i) * SS;
        const float* Bp = g_lc + (b * 6 + j) * SS;
        float part = 0.0f;
        for (int s = lane; s < SS; s += 32) {
            float a = fmaxf((A[s] - mi) / di * gi + bi, 0.0f);
            float c = fmaxf((Bp[s] - mj) / dj * gj + bj, 0.0f);
            float d = a - c;
            part += d * d;
        }
#pragma unroll
        for (int o = 16; o; o >>= 1) part += __shfl_down_sync(FULLMASK, part, o);
        if (lane == 0) {
            float v = part > 0.0f ? sqrtf(part) : 0.0f;   // zero-safe
            g_tf[b * 36 + i * 6 + j] = v;
            g_tf[b * 36 + j * 6 + i] = v;
        }
    }

    // ---- completion counter: last block performs BN2 + output + reset ----
    __syncthreads();
    if (t == 0) {
        __threadfence();
        s_last = (atomicAdd(&g_done, 1) == BB - 1) ? 1 : 0;
    }
    __syncthreads();
    if (!s_last) return;
    __threadfence();                              // acquire all g_tf writes

    if (t < 36) {
        float m = 0.0f;
        for (int bb = 0; bb < BB; bb++) m += g_tf[bb * 36 + t];
        m /= (float)BB;
        float v = 0.0f;
        for (int bb = 0; bb < BB; bb++) {
            float d = g_tf[bb * 36 + t] - m;
            v += d * d;
        }
        v /= (float)BB;
        s_m[t] = m; s_v[t] = v;
    }
    __syncthreads();
    for (int i = t; i < BB * 36; i += 512) {
        int f = i % 36;
        float x = g_tf[i];
        float y = (x - s_m[f]) / sqrtf(s_v[f] + 1e-5f) * bn2g[f] + bn2b[f];
        out[i] = fmaxf(y, 0.0f);
    }
    // reset pipeline state for next replay
    if (t >= 64 && t < 64 + BB * 32) g_prog[t - 64] = 0;
    if (t >= 32 && t < 44) g_ch[t - 32] = 0.0;
    if (t == 0) { g_acc[0] = 0.0; g_acc[1] = 0.0; g_done = 0; }
}

// =====================================================================
extern "C" void kernel_launch(void* const* d_in, const int* in_sizes, int n_in,
                              void* d_out, int out_size)
{
    const float* xyz  = (const float*)d_in[0];
    const float* bn1g = (const float*)d_in[1];
    const float* bn1b = (const float*)d_in[2];
    const float* bn2g = (const float*)d_in[3];
    const float* bn2b = (const float*)d_in[4];
    float* out = (float*)d_out;

    // idempotent host-side attribute set (capture-safe)
    cudaFuncSetAttribute(fused_kernel, cudaFuncAttributeMaxDynamicSharedMemorySize,
                         NN * 16);

    fused_kernel<<<BB + BB * 8, 1024, NN * 16>>>(xyz);     // 144 blocks
    finalize1_kernel<<<64, 256>>>();
    finalize2_kernel<<<BB, 512>>>(bn1g, bn1b, bn2g, bn2b, out);
}

// round 15
// speedup vs baseline: 1.0129x; 1.0129x over previous
#include <cuda_runtime.h>
#include <cuda_bf16.h>

#define BB 16
#define NN 8192
#define SS 1024
#define KK 32
#define FULLMASK 0xFFFFFFFFu
typedef unsigned long long ull;

// ---------------- scratch (no allocs allowed) ----------------
__device__ float  g_newxyz[BB * SS * 3];   // FPS-selected centers
__device__ float  g_gmax[BB * SS * 3];     // max over K of diff, per coord
__device__ float  g_gsum[BB * SS * 3];     // sum over K of diff, per coord
__device__ double g_acc[2];                // sum(diff), sum(diff^2) for global std
__device__ float  g_lc[BB * 6 * SS];       // pooled features (raw, pre-BN1)
__device__ int    g_prog[BB * 32];         // progress, one 128B line per batch
__device__ double g_ch[12];                // BN1 per-channel sum[6], sumsq[6]
__device__ float  g_tf[BB * 36];           // cdist features pre-BN2
__device__ int    g_done;                  // finalize2 completion counter

// ---------------- f32x2 helpers (Blackwell packed fp32) ----------------
__device__ __forceinline__ ull pk2(float lo, float hi) {
    ull r;
    asm("mov.b64 %0, {%1, %2};" : "=l"(r) : "f"(lo), "f"(hi));
    return r;
}
__device__ __forceinline__ void upk2(float& lo, float& hi, ull v) {
    asm("mov.b64 {%0, %1}, %2;" : "=f"(lo), "=f"(hi) : "l"(v));
}
__device__ __forceinline__ ull add2(ull a, ull b) {
    ull r;
    asm("add.rn.f32x2 %0, %1, %2;" : "=l"(r) : "l"(a), "l"(b));
    return r;
}
__device__ __forceinline__ ull mul2(ull a, ull b) {
    ull r;
    asm("mul.rn.f32x2 %0, %1, %2;" : "=l"(r) : "l"(a), "l"(b));
    return r;
}

// ---------------- release/acquire progress channel ----------------
__device__ __forceinline__ void st_rel_gpu(int* p, int v) {
    asm volatile("st.release.gpu.s32 [%0], %1;" :: "l"(p), "r"(v) : "memory");
}
__device__ __forceinline__ int ld_acq_gpu(const int* p) {
    int v;
    asm volatile("ld.acquire.gpu.s32 %0, [%1];" : "=r"(v) : "l"(p) : "memory");
    return v;
}

// ---------------- top-k machinery (R9, proven) ----------------
__device__ __forceinline__ ull u64min(ull a, ull b) { return a < b ? a : b; }
__device__ __forceinline__ ull u64max(ull a, ull b) { return a < b ? b : a; }
__device__ __forceinline__ ull makekey(float d, int idx) {
    unsigned ub = __float_as_uint(d);
    ub ^= ((unsigned)((int)ub >> 31)) | 0x80000000u;
    return ((ull)ub << 13) | (unsigned)idx;
}
__device__ __forceinline__ float kth2kd(ull kth) {
    unsigned ub = (unsigned)(kth >> 13);
    unsigned db = (ub >> 31) ? (ub ^ 0x80000000u) : ~ub;
    return __uint_as_float(db);
}
__device__ __forceinline__ ull sort32(ull key, int lane)
{
#pragma unroll
    for (int k = 2; k <= 32; k <<= 1) {
#pragma unroll
        for (int j = k >> 1; j > 0; j >>= 1) {
            ull other = __shfl_xor_sync(FULLMASK, key, j);
            bool up = ((lane & k) == 0);
            bool takeMin = (((lane & j) == 0) == up);
            key = takeMin ? u64min(key, other) : u64max(key, other);
        }
    }
    return key;
}
__device__ __forceinline__ ull merge32(ull key, ull buf, int lane)
{
    buf = sort32(buf, lane);
    ull rev = __shfl_sync(FULLMASK, buf, 31 - lane);
    key = u64min(key, rev);
#pragma unroll
    for (int j = 16; j > 0; j >>= 1) {
        ull other = __shfl_xor_sync(FULLMASK, key, j);
        bool takeMin = ((lane & j) == 0);
        key = takeMin ? u64min(key, other) : u64max(key, other);
    }
    return key;
}
__device__ __forceinline__ void push_chunk(ull ck, unsigned m, int lane,
                                           ull& key, float& kd,
                                           ull& buf, int& bcnt)
{
    int cnt = __popc(m);
    int r = lane - bcnt;
    bool take = (r >= 0) && (r < cnt);
    unsigned pos = __fns(m, 0, take ? (r + 1) : 1);
    ull got = __shfl_sync(FULLMASK, ck, pos & 31);
    if (take) buf = got;
    bcnt += cnt;
    if (bcnt >= 32) {
        key = merge32(key, buf, lane);
        ull kth = __shfl_sync(FULLMASK, key, 31);
        kd = kth2kd(kth);
        int left = bcnt - 32;
        buf = ~0ull;
        if (left) {   // re-push overflow candidates (extras are harmless)
            int start = cnt - left;
            bool tk2 = lane < left;
            unsigned pos2 = __fns(m, 0, tk2 ? (start + lane + 1) : 1);
            ull got2 = __shfl_sync(FULLMASK, ck, pos2 & 31);
            if (tk2) buf = got2;
        }
        bcnt = left;
    }
}

// wait until g_prog[b*32] >= target: progressive estimated sleep
// (~0.4us/step conservative vs measured ~0.68us/step), capped 100us.
__device__ __forceinline__ void wait_progress(int b, int target)
{
    int cur = ld_acq_gpu(&g_prog[b * 32]);
    while (cur < target) {
        unsigned rem = (unsigned)(target - cur);
        unsigned ns = rem * 400u;
        if (ns > 100000u) ns = 100000u;
        if (ns < 2000u) ns = 2000u;
        __nanosleep(ns);
        cur = ld_acq_gpu(&g_prog[b * 32]);
    }
}

// =====================================================================
// Fused producer/consumer kernel (R12 structure — measured best).
// 144 blocks x 1024 threads (all resident in wave 1 -> deadlock-free).
//   blocks 0..15   : FPS for batch b (exact R4 math), publishes
//                    g_prog[b*32] every 16 steps via st.release.gpu.
//   blocks 16..143 : kNN (R9 pairing); warps wait via progressive
//                    estimated sleep + ld.acquire.gpu.
// Results are bit-identical to the sequential version.
// =====================================================================
__global__ void __launch_bounds__(1024) fused_kernel(const float* __restrict__ xyz)
{
    extern __shared__ char dyn_smem[];
    const int t = threadIdx.x;
    const int lane = t & 31, warp = t >> 5;

    if (blockIdx.x < BB) {
        // ---------------- FPS path (R12 verbatim) ----------------
        const int b = blockIdx.x;
        const float* X = xyz + (size_t)b * NN * 3;

        ull px2[4], py2[4], pz2[4];
        float dist[8];
#pragma unroll
        for (int i = 0; i < 4; i++) {
            int p0 = t + 1024 * (2 * i);
            int p1 = t + 1024 * (2 * i + 1);
            px2[i] = pk2(X[p0 * 3 + 0], X[p1 * 3 + 0]);
            py2[i] = pk2(X[p0 * 3 + 1], X[p1 * 3 + 1]);
            pz2[i] = pk2(X[p0 * 3 + 2], X[p1 * 3 + 2]);
            dist[2 * i] = 1e10f;
            dist[2 * i + 1] = 1e10f;
        }

        __shared__ unsigned s_val[2][32];
        __shared__ int      s_idx[2][32];

        float cx = X[0], cy = X[1], cz = X[2];   // sample 0 = point 0
        if (t == 0) {
            float* o = g_newxyz + (size_t)(b * SS) * 3;
            o[0] = cx; o[1] = cy; o[2] = cz;
        }

        for (int s = 0; s < SS - 1; s++) {
            const ull ncx2 = pk2(-cx, -cx);
            const ull ncy2 = pk2(-cy, -cy);
            const ull ncz2 = pk2(-cz, -cz);

            float bestv = -1.0f;
#pragma unroll
            for (int i = 0; i < 4; i++) {
                ull dx2 = add2(px2[i], ncx2);
                ull dy2 = add2(py2[i], ncy2);
                ull dz2 = add2(pz2[i], ncz2);
                ull d2 = add2(add2(mul2(dx2, dx2), mul2(dy2, dy2)), mul2(dz2, dz2));
                float d0, d1;
                upk2(d0, d1, d2);
                float n0 = fminf(dist[2 * i], d0);
                float n1 = fminf(dist[2 * i + 1], d1);
                dist[2 * i] = n0;
                dist[2 * i + 1] = n1;
                bestv = fmaxf(bestv, fmaxf(n0, n1));
            }

            unsigned wm = __reduce_max_sync(FULLMASK, __float_as_uint(bestv));
            float wmf = __uint_as_float(wm);
            unsigned cand = 0x7FFFFFFFu;
#pragma unroll
            for (int sl = 7; sl >= 0; sl--)
                cand = (dist[sl] == wmf) ? (unsigned)(t + (sl << 10)) : cand;
            cand = __reduce_min_sync(FULLMASK, cand);

            if (lane == 0) { s_val[s & 1][warp] = wm; s_idx[s & 1][warp] = (int)cand; }
            __syncthreads();

            unsigned v = s_val[s & 1][lane];
            int      ci = s_idx[s & 1][lane];
            unsigned gm = __reduce_max_sync(FULLMASK, v);
            unsigned cc = (v == gm) ? (unsigned)ci : 0x7FFFFFFFu;
            int widx = (int)__reduce_min_sync(FULLMASK, cc);

            cx = X[widx * 3 + 0];
            cy = X[widx * 3 + 1];
            cz = X[widx * 3 + 2];
            if (t == 0) {
                float* o = g_newxyz + (size_t)(b * SS + s + 1) * 3;
                o[0] = cx; o[1] = cy; o[2] = cz;
                if ((s & 15) == 15)             // publish progress (release)
                    st_rel_gpu(&g_prog[b * 32], s + 2);
            }
        }
        if (t == 0) st_rel_gpu(&g_prog[b * 32], SS);   // final publish
        return;
    }

    // ---------------- kNN path ----------------
    ulonglong2* sxy = (ulonglong2*)dyn_smem;          // [NN/2] {x2, y2}
    ulonglong2* szw = (ulonglong2*)dyn_smem + NN / 2; // [NN/2] {z2, sq2}
    __shared__ double s_p1[32], s_p2[32];

    const int kb = blockIdx.x - BB;
    const int b  = kb >> 3;                    // 8 blocks per batch
    const int qc = kb & 7;
    const float* X = xyz + (size_t)b * NN * 3;

    for (int j = t; j < NN / 2; j += 1024) {
        const float* p = X + 6 * j;
        float x0 = p[0], y0 = p[1], z0 = p[2];
        float x1 = p[3], y1 = p[4], z1 = p[5];
        float sq0 = __fadd_rn(__fadd_rn(__fmul_rn(x0, x0), __fmul_rn(y0, y0)),
                              __fmul_rn(z0, z0));
        float sq1 = __fadd_rn(__fadd_rn(__fmul_rn(x1, x1), __fmul_rn(y1, y1)),
                              __fmul_rn(z1, z1));
        sxy[j] = make_ulonglong2(pk2(x0, x1), pk2(y0, y1));
        szw[j] = make_ulonglong2(pk2(z0, z1), pk2(sq0, sq1));
    }
    __syncthreads();

    const ull m2two = pk2(-2.0f, -2.0f);
    const int g = qc * 32 + warp;              // 0..255 per batch

    double acc1 = 0.0, acc2 = 0.0;             // meaningful on lane 0 only

    for (int qp = 0; qp < 2; qp++) {
        const int s0 = (qp ? 512 : 0) + 2 * g;
        const int s1 = s0 + 1;

        // wait for fps to publish centroids s0, s1
        wait_progress(b, s1 + 1);

        const float* cen0 = g_newxyz + (size_t)(b * SS + s0) * 3;
        const float* cen1 = g_newxyz + (size_t)(b * SS + s1) * 3;
        const float ax = cen0[0], ay = cen0[1], az = cen0[2];
        const float bx = cen1[0], by = cen1[1], bz = cen1[2];
        const float asq = __fadd_rn(__fadd_rn(__fmul_rn(ax, ax), __fmul_rn(ay, ay)),
                                    __fmul_rn(az, az));
        const float bsq = __fadd_rn(__fadd_rn(__fmul_rn(bx, bx), __fmul_rn(by, by)),
                                    __fmul_rn(bz, bz));
        const ull aX2 = pk2(ax, ax), aY2 = pk2(ay, ay), aZ2 = pk2(az, az);
        const ull aS2 = pk2(asq, asq);
        const ull bX2 = pk2(bx, bx), bY2 = pk2(by, by), bZ2 = pk2(bz, bz);
        const ull bS2 = pk2(bsq, bsq);

        ull key0, key1;
        float kd0, kd1;
        {
            ulonglong2 A = sxy[lane];
            ulonglong2 B = szw[lane];
            ull dot0 = add2(add2(mul2(A.x, aX2), mul2(A.y, aY2)), mul2(B.x, aZ2));
            ull dd0 = add2(add2(mul2(m2two, dot0), aS2), B.y);
            ull dot1 = add2(add2(mul2(A.x, bX2), mul2(A.y, bY2)), mul2(B.x, bZ2));
            ull dd1 = add2(add2(mul2(m2two, dot1), bS2), B.y);
            float de, dq;
            upk2(de, dq, dd0);
            key0 = sort32(makekey(de, 2 * lane), lane);
            key0 = merge32(key0, makekey(dq, 2 * lane + 1), lane);
            kd0 = kth2kd(__shfl_sync(FULLMASK, key0, 31));
            upk2(de, dq, dd1);
            key1 = sort32(makekey(de, 2 * lane), lane);
            key1 = merge32(key1, makekey(dq, 2 * lane + 1), lane);
            kd1 = kth2kd(__shfl_sync(FULLMASK, key1, 31));
        }
        ull buf0 = ~0ull, buf1 = ~0ull;
        int bc0 = 0, bc1 = 0;

        for (int jb = 32; jb < NN / 2; jb += 32) {
            const int j = jb + lane;           // cands 2j, 2j+1
            ulonglong2 A = sxy[j];
            ulonglong2 B = szw[j];
            ull dot0 = add2(add2(mul2(A.x, aX2), mul2(A.y, aY2)), mul2(B.x, aZ2));
            ull dd0 = add2(add2(mul2(m2two, dot0), aS2), B.y);
            ull dot1 = add2(add2(mul2(A.x, bX2), mul2(A.y, bY2)), mul2(B.x, bZ2));
            ull dd1 = add2(add2(mul2(m2two, dot1), bS2), B.y);
            float d0e, d0o, d1e, d1o;
            upk2(d0e, d0o, dd0);
            upk2(d1e, d1o, dd1);
            bool hit = (d0e <= kd0) | (d0o <= kd0) | (d1e <= kd1) | (d1o <= kd1);
            if (__any_sync(FULLMASK, hit)) {
                unsigned m;
                m = __ballot_sync(FULLMASK, d0e <= kd0);
                if (m) push_chunk(makekey(d0e, 2 * j), m, lane, key0, kd0, buf0, bc0);
                m = __ballot_sync(FULLMASK, d0o <= kd0);
                if (m) push_chunk(makekey(d0o, 2 * j + 1), m, lane, key0, kd0, buf0, bc0);
                m = __ballot_sync(FULLMASK, d1e <= kd1);
                if (m) push_chunk(makekey(d1e, 2 * j), m, lane, key1, kd1, buf1, bc1);
                m = __ballot_sync(FULLMASK, d1o <= kd1);
                if (m) push_chunk(makekey(d1o, 2 * j + 1), m, lane, key1, kd1, buf1, bc1);
            }
        }
        if (bc0 > 0) key0 = merge32(key0, buf0, lane);
        if (bc1 > 0) key1 = merge32(key1, buf1, lane);

        // ----- group stats for both queries -----
#pragma unroll
        for (int q = 0; q < 2; q++) {
            ull key = q ? key1 : key0;
            float cx = q ? bx : ax, cy = q ? by : ay, cz = q ? bz : az;
            int sq = q ? s1 : s0;
            int ki = (int)(key & 0x1FFFull);
            ulonglong2 P1 = sxy[ki >> 1];
            ulonglong2 P2 = szw[ki >> 1];
            float xl, xh, yl, yh, zl, zh;
            upk2(xl, xh, P1.x);
            upk2(yl, yh, P1.y);
            upk2(zl, zh, P2.x);
            float px = (ki & 1) ? xh : xl;
            float py = (ki & 1) ? yh : yl;
            float pz = (ki & 1) ? zh : zl;
            float dx = __fsub_rn(px, cx);
            float dy = __fsub_rn(py, cy);
            float dz = __fsub_rn(pz, cz);
            float sdx = dx, sdy = dy, sdz = dz;
            float mdx = dx, mdy = dy, mdz = dz;
            float t1 = dx + dy + dz;
            float t2 = dx * dx + dy * dy + dz * dz;
#pragma unroll
            for (int o = 16; o; o >>= 1) {
                sdx += __shfl_down_sync(FULLMASK, sdx, o);
                sdy += __shfl_down_sync(FULLMASK, sdy, o);
                sdz += __shfl_down_sync(FULLMASK, sdz, o);
                mdx = fmaxf(mdx, __shfl_down_sync(FULLMASK, mdx, o));
                mdy = fmaxf(mdy, __shfl_down_sync(FULLMASK, mdy, o));
                mdz = fmaxf(mdz, __shfl_down_sync(FULLMASK, mdz, o));
                t1 += __shfl_down_sync(FULLMASK, t1, o);
                t2 += __shfl_down_sync(FULLMASK, t2, o);
            }
            if (lane == 0) {
                int ix = (b * SS + sq) * 3;
                g_gsum[ix] = sdx; g_gsum[ix + 1] = sdy; g_gsum[ix + 2] = sdz;
                g_gmax[ix] = mdx; g_gmax[ix + 1] = mdy; g_gmax[ix + 2] = mdz;
                acc1 += (double)t1;
                acc2 += (double)t2;
            }
        }
    }

    if (lane == 0) { s_p1[warp] = acc1; s_p2[warp] = acc2; }
    __syncthreads();
    if (t == 0) {
        double a = 0.0, c = 0.0;
        for (int w = 0; w < 32; w++) { a += s_p1[w]; c += s_p2[w]; }
        atomicAdd(&g_acc[0], a);
        atomicAdd(&g_acc[1], c);
    }
}

// =====================================================================
// K3a: lc build (64 blocks) + BN1 channel sum/sumsq via double atomics.
// =====================================================================
__global__ void __launch_bounds__(256) finalize1_kernel()
{
    const int t = threadIdx.x;
    const int lane = t & 31, warp = t >> 5;
    const int idx = blockIdx.x * 256 + t;     // 0..16383
    __shared__ float s_red[12][8];

    double M = (double)BB * SS * KK * 3;
    double var = (g_acc[1] - g_acc[0] * g_acc[0] / M) / (M - 1.0);  // ddof=1
    const float se = (float)sqrt(var) + 1e-5f;

    int b = idx >> 10, s = idx & (SS - 1);
    const float* gm = g_gmax + idx * 3;
    const float* gs = g_gsum + idx * 3;
    const float* cn = g_newxyz + idx * 3;
    float v[6];
#pragma unroll
    for (int c = 0; c < 3; c++) {
        float mx = __fdiv_rn(gm[c], se);
        float mn = __fdiv_rn(__fdiv_rn(gs[c], 32.0f), se);
        v[c] = __fadd_rn(mx, mn);
        g_lc[(b * 6 + c) * SS + s] = v[c];
    }
#pragma unroll
    for (int c = 0; c < 3; c++) {
        float w = cn[c];
        v[3 + c] = w + w;
        g_lc[(b * 6 + 3 + c) * SS + s] = v[3 + c];
    }

    float sm[12];
#pragma unroll
    for (int c = 0; c < 6; c++) { sm[c] = v[c]; sm[6 + c] = v[c] * v[c]; }
#pragma unroll
    for (int k = 0; k < 12; k++) {
#pragma unroll
        for (int o = 16; o; o >>= 1) sm[k] += __shfl_down_sync(FULLMASK, sm[k], o);
        if (lane == 0) s_red[k][warp] = sm[k];
    }
    __syncthreads();
    if (t < 12) {
        double tot = 0.0;
        for (int w = 0; w < 8; w++) tot += (double)s_red[t][w];
        atomicAdd(&g_ch[t], tot);
    }
}

// =====================================================================
// K3b: cdist with on-the-fly BN1 normalize+relu (16 blocks, one per
// batch); the LAST block to finish also does BN2 + output + resets.
// =====================================================================
__global__ void __launch_bounds__(512) finalize2_kernel(
    const float* __restrict__ bn1g, const float* __restrict__ bn1b,
    const float* __restrict__ bn2g, const float* __restrict__ bn2b,
    float* __restrict__ out)
{
    const int b = blockIdx.x;
    const int t = threadIdx.x, lane = t & 31, warp = t >> 5;
    __shared__ int s_last;
    __shared__ float s_m[36], s_v[36];

    if (t < 6) g_tf[b * 36 + t * 7] = 0.0f;      // diagonal

    if (warp < 15) {
        int i = 0, j = 0, p = warp;
        for (i = 0; i < 5; i++) {
            int row = 5 - i;
            if (p < row) { j = i + 1 + p; break; }
            p -= row;
        }
        const double Ninv = 1.0 / (double)(BB * SS);
        double mid = g_ch[i] * Ninv;
        double vid = g_ch[6 + i] * Ninv - mid * mid;   // biased var
        double mjd = g_ch[j] * Ninv;
        double vjd = g_ch[6 + j] * Ninv - mjd * mjd;
        float mi = (float)mid, di = (float)sqrt(vid + 1e-5);
        float mj = (float)mjd, dj = (float)sqrt(vjd + 1e-5);
        float gi = bn1g[i], bi = bn1b[i];
        float gj = bn1g[j], bj = bn1b[j];

        const float* A  = g_lc + (b * 6 + i) * SS;
        const float* Bp = g_lc + (b * 6 + j) * SS;
        float part = 0.0f;
        for (int s = lane; s < SS; s += 32) {
            float a = fmaxf((A[s] - mi) / di * gi + bi, 0.0f);
            float c = fmaxf((Bp[s] - mj) / dj * gj + bj, 0.0f);
            float d = a - c;
            part += d * d;
        }
#pragma unroll
        for (int o = 16; o; o >>= 1) part += __shfl_down_sync(FULLMASK, part, o);
        if (lane == 0) {
            float v = part > 0.0f ? sqrtf(part) : 0.0f;   // zero-safe
            g_tf[b * 36 + i * 6 + j] = v;
            g_tf[b * 36 + j * 6 + i] = v;
        }
    }

    // ---- completion counter: last block performs BN2 + output + reset ----
    __syncthreads();
    if (t == 0) {
        __threadfence();
        s_last = (atomicAdd(&g_done, 1) == BB - 1) ? 1 : 0;
    }
    __syncthreads();
    if (!s_last) return;
    __threadfence();                              // acquire all g_tf writes

    if (t < 36) {
        float m = 0.0f;
        for (int bb = 0; bb < BB; bb++) m += g_tf[bb * 36 + t];
        m /= (float)BB;
        float v = 0.0f;
        for (int bb = 0; bb < BB; bb++) {
            float d = g_tf[bb * 36 + t] - m;
            v += d * d;
        }
        v /= (float)BB;
        s_m[t] = m; s_v[t] = v;
    }
    __syncthreads();
    for (int i = t; i < BB * 36; i += 512) {
        int f = i % 36;
        float x = g_tf[i];
        float y = (x - s_m[f]) / sqrtf(s_v[f] + 1e-5f) * bn2g[f] + bn2b[f];
        out[i] = fmaxf(y, 0.0f);
    }
    // reset pipeline state for next replay
    if (t >= 64 && t < 64 + BB * 32) g_prog[t - 64] = 0;
    if (t >= 32 && t < 44) g_ch[t - 32] = 0.0;
    if (t == 0) { g_acc[0] = 0.0; g_acc[1] = 0.0; g_done = 0; }
}

// =====================================================================
extern "C" void kernel_launch(void* const* d_in, const int* in_sizes, int n_in,
                              void* d_out, int out_size)
{
    const float* xyz  = (const float*)d_in[0];
    const float* bn1g = (const float*)d_in[1];
    const float* bn1b = (const float*)d_in[2];
    const float* bn2g = (const float*)d_in[3];
    const float* bn2b = (const float*)d_in[4];
    float* out = (float*)d_out;

    // idempotent host-side attribute set (capture-safe)
    cudaFuncSetAttribute(fused_kernel, cudaFuncAttributeMaxDynamicSharedMemorySize,
                         NN * 16);

    fused_kernel<<<BB + BB * 8, 1024, NN * 16>>>(xyz);     // 144 blocks
    finalize1_kernel<<<64, 256>>>();
    finalize2_kernel<<<BB, 512>>>(bn1g, bn1b, bn2g, bn2b, out);
}

// round 16
// speedup vs baseline: 1.0159x; 1.0030x over previous
#include <cuda_runtime.h>
#include <cuda_bf16.h>

#define BB 16
#define NN 8192
#define SS 1024
#define KK 32
#define FULLMASK 0xFFFFFFFFu
typedef unsigned long long ull;

// ---------------- scratch (no allocs allowed) ----------------
__device__ float  g_newxyz[BB * SS * 3];   // FPS-selected centers
__device__ float  g_gmax[BB * SS * 3];     // max over K of diff, per coord
__device__ float  g_gsum[BB * SS * 3];     // sum over K of diff, per coord
__device__ double g_acc[2];                // sum(diff), sum(diff^2) for global std
__device__ float  g_lc[BB * 6 * SS];       // pooled features (raw, pre-BN1)
__device__ int    g_prog[BB * 32];         // progress, one 128B line per batch
__device__ double g_ch[12];                // BN1 per-channel sum[6], sumsq[6]
__device__ float  g_tf[BB * 36];           // cdist features pre-BN2
__device__ int    g_done;                  // finalize2 completion counter

// ---------------- f32x2 helpers (Blackwell packed fp32) ----------------
__device__ __forceinline__ ull pk2(float lo, float hi) {
    ull r;
    asm("mov.b64 %0, {%1, %2};" : "=l"(r) : "f"(lo), "f"(hi));
    return r;
}
__device__ __forceinline__ void upk2(float& lo, float& hi, ull v) {
    asm("mov.b64 {%0, %1}, %2;" : "=f"(lo), "=f"(hi) : "l"(v));
}
__device__ __forceinline__ ull add2(ull a, ull b) {
    ull r;
    asm("add.rn.f32x2 %0, %1, %2;" : "=l"(r) : "l"(a), "l"(b));
    return r;
}
__device__ __forceinline__ ull mul2(ull a, ull b) {
    ull r;
    asm("mul.rn.f32x2 %0, %1, %2;" : "=l"(r) : "l"(a), "l"(b));
    return r;
}

// ---------------- release/acquire progress channel ----------------
__device__ __forceinline__ void st_rel_gpu(int* p, int v) {
    asm volatile("st.release.gpu.s32 [%0], %1;" :: "l"(p), "r"(v) : "memory");
}
__device__ __forceinline__ int ld_acq_gpu(const int* p) {
    int v;
    asm volatile("ld.acquire.gpu.s32 %0, [%1];" : "=r"(v) : "l"(p) : "memory");
    return v;
}

// ---------------- top-k machinery (R9, proven) ----------------
__device__ __forceinline__ ull u64min(ull a, ull b) { return a < b ? a : b; }
__device__ __forceinline__ ull u64max(ull a, ull b) { return a < b ? b : a; }
__device__ __forceinline__ ull makekey(float d, int idx) {
    unsigned ub = __float_as_uint(d);
    ub ^= ((unsigned)((int)ub >> 31)) | 0x80000000u;
    return ((ull)ub << 13) | (unsigned)idx;
}
__device__ __forceinline__ float kth2kd(ull kth) {
    unsigned ub = (unsigned)(kth >> 13);
    unsigned db = (ub >> 31) ? (ub ^ 0x80000000u) : ~ub;
    return __uint_as_float(db);
}
__device__ __forceinline__ ull sort32(ull key, int lane)
{
#pragma unroll
    for (int k = 2; k <= 32; k <<= 1) {
#pragma unroll
        for (int j = k >> 1; j > 0; j >>= 1) {
            ull other = __shfl_xor_sync(FULLMASK, key, j);
            bool up = ((lane & k) == 0);
            bool takeMin = (((lane & j) == 0) == up);
            key = takeMin ? u64min(key, other) : u64max(key, other);
        }
    }
    return key;
}
__device__ __forceinline__ ull merge32(ull key, ull buf, int lane)
{
    buf = sort32(buf, lane);
    ull rev = __shfl_sync(FULLMASK, buf, 31 - lane);
    key = u64min(key, rev);
#pragma unroll
    for (int j = 16; j > 0; j >>= 1) {
        ull other = __shfl_xor_sync(FULLMASK, key, j);
        bool takeMin = ((lane & j) == 0);
        key = takeMin ? u64min(key, other) : u64max(key, other);
    }
    return key;
}
__device__ __forceinline__ void push_chunk(ull ck, unsigned m, int lane,
                                           ull& key, float& kd,
                                           ull& buf, int& bcnt)
{
    int cnt = __popc(m);
    int r = lane - bcnt;
    bool take = (r >= 0) && (r < cnt);
    unsigned pos = __fns(m, 0, take ? (r + 1) : 1);
    ull got = __shfl_sync(FULLMASK, ck, pos & 31);
    if (take) buf = got;
    bcnt += cnt;
    if (bcnt >= 32) {
        key = merge32(key, buf, lane);
        ull kth = __shfl_sync(FULLMASK, key, 31);
        kd = kth2kd(kth);
        int left = bcnt - 32;
        buf = ~0ull;
        if (left) {   // re-push overflow candidates (extras are harmless)
            int start = cnt - left;
            bool tk2 = lane < left;
            unsigned pos2 = __fns(m, 0, tk2 ? (start + lane + 1) : 1);
            ull got2 = __shfl_sync(FULLMASK, ck, pos2 & 31);
            if (tk2) buf = got2;
        }
        bcnt = left;
    }
}

// wait until g_prog[b*32] >= target: progressive estimated sleep
// (~0.4us/step conservative vs measured ~0.68us/step), capped 100us.
__device__ __forceinline__ void wait_progress(int b, int target)
{
    int cur = ld_acq_gpu(&g_prog[b * 32]);
    while (cur < target) {
        unsigned rem = (unsigned)(target - cur);
        unsigned ns = rem * 400u;
        if (ns > 100000u) ns = 100000u;
        if (ns < 2000u) ns = 2000u;
        __nanosleep(ns);
        cur = ld_acq_gpu(&g_prog[b * 32]);
    }
}

// =====================================================================
// Fused producer/consumer kernel. 80 blocks x 1024 threads (all
// resident in wave 1 -> deadlock-free). Fewer concurrent kNN blocks
// (64 vs 128) lowers chip power so the fps critical path clocks higher;
// total kNN work unchanged and still hidden under fps.
//   blocks 0..15  : FPS for batch b (R12-verbatim), publishes
//                   g_prog[b*32] every 16 steps via st.release.gpu.
//   blocks 16..79 : kNN (R9 pairing), 8 queries/warp as 4 pairs;
//                   progressive-sleep waits.
// Results are bit-identical to the sequential version.
// =====================================================================
__global__ void __launch_bounds__(1024) fused_kernel(const float* __restrict__ xyz)
{
    extern __shared__ char dyn_smem[];
    const int t = threadIdx.x;
    const int lane = t & 31, warp = t >> 5;

    if (blockIdx.x < BB) {
        // ---------------- FPS path (R12 verbatim) ----------------
        const int b = blockIdx.x;
        const float* X = xyz + (size_t)b * NN * 3;

        ull px2[4], py2[4], pz2[4];
        float dist[8];
#pragma unroll
        for (int i = 0; i < 4; i++) {
            int p0 = t + 1024 * (2 * i);
            int p1 = t + 1024 * (2 * i + 1);
            px2[i] = pk2(X[p0 * 3 + 0], X[p1 * 3 + 0]);
            py2[i] = pk2(X[p0 * 3 + 1], X[p1 * 3 + 1]);
            pz2[i] = pk2(X[p0 * 3 + 2], X[p1 * 3 + 2]);
            dist[2 * i] = 1e10f;
            dist[2 * i + 1] = 1e10f;
        }

        __shared__ unsigned s_val[2][32];
        __shared__ int      s_idx[2][32];

        float cx = X[0], cy = X[1], cz = X[2];   // sample 0 = point 0
        if (t == 0) {
            float* o = g_newxyz + (size_t)(b * SS) * 3;
            o[0] = cx; o[1] = cy; o[2] = cz;
        }

        for (int s = 0; s < SS - 1; s++) {
            const ull ncx2 = pk2(-cx, -cx);
            const ull ncy2 = pk2(-cy, -cy);
            const ull ncz2 = pk2(-cz, -cz);

            float bestv = -1.0f;
#pragma unroll
            for (int i = 0; i < 4; i++) {
                ull dx2 = add2(px2[i], ncx2);
                ull dy2 = add2(py2[i], ncy2);
                ull dz2 = add2(pz2[i], ncz2);
                ull d2 = add2(add2(mul2(dx2, dx2), mul2(dy2, dy2)), mul2(dz2, dz2));
                float d0, d1;
                upk2(d0, d1, d2);
                float n0 = fminf(dist[2 * i], d0);
                float n1 = fminf(dist[2 * i + 1], d1);
                dist[2 * i] = n0;
                dist[2 * i + 1] = n1;
                bestv = fmaxf(bestv, fmaxf(n0, n1));
            }

            unsigned wm = __reduce_max_sync(FULLMASK, __float_as_uint(bestv));
            float wmf = __uint_as_float(wm);
            unsigned cand = 0x7FFFFFFFu;
#pragma unroll
            for (int sl = 7; sl >= 0; sl--)
                cand = (dist[sl] == wmf) ? (unsigned)(t + (sl << 10)) : cand;
            cand = __reduce_min_sync(FULLMASK, cand);

            if (lane == 0) { s_val[s & 1][warp] = wm; s_idx[s & 1][warp] = (int)cand; }
            __syncthreads();

            unsigned v = s_val[s & 1][lane];
            int      ci = s_idx[s & 1][lane];
            unsigned gm = __reduce_max_sync(FULLMASK, v);
            unsigned cc = (v == gm) ? (unsigned)ci : 0x7FFFFFFFu;
            int widx = (int)__reduce_min_sync(FULLMASK, cc);

            cx = X[widx * 3 + 0];
            cy = X[widx * 3 + 1];
            cz = X[widx * 3 + 2];
            if (t == 0) {
                float* o = g_newxyz + (size_t)(b * SS + s + 1) * 3;
                o[0] = cx; o[1] = cy; o[2] = cz;
                if ((s & 15) == 15)             // publish progress (release)
                    st_rel_gpu(&g_prog[b * 32], s + 2);
            }
        }
        if (t == 0) st_rel_gpu(&g_prog[b * 32], SS);   // final publish
        return;
    }

    // ---------------- kNN path (64 blocks, 4 per batch) ----------------
    ulonglong2* sxy = (ulonglong2*)dyn_smem;          // [NN/2] {x2, y2}
    ulonglong2* szw = (ulonglong2*)dyn_smem + NN / 2; // [NN/2] {z2, sq2}
    __shared__ double s_p1[32], s_p2[32];

    const int kb = blockIdx.x - BB;
    const int b  = kb >> 2;                    // 4 blocks per batch
    const int qc = kb & 3;
    const float* X = xyz + (size_t)b * NN * 3;

    for (int j = t; j < NN / 2; j += 1024) {
        const float* p = X + 6 * j;
        float x0 = p[0], y0 = p[1], z0 = p[2];
        float x1 = p[3], y1 = p[4], z1 = p[5];
        float sq0 = __fadd_rn(__fadd_rn(__fmul_rn(x0, x0), __fmul_rn(y0, y0)),
                              __fmul_rn(z0, z0));
        float sq1 = __fadd_rn(__fadd_rn(__fmul_rn(x1, x1), __fmul_rn(y1, y1)),
                              __fmul_rn(z1, z1));
        sxy[j] = make_ulonglong2(pk2(x0, x1), pk2(y0, y1));
        szw[j] = make_ulonglong2(pk2(z0, z1), pk2(sq0, sq1));
    }
    __syncthreads();

    const ull m2two = pk2(-2.0f, -2.0f);
    const int g = qc * 32 + warp;              // 0..127 per batch

    double acc1 = 0.0, acc2 = 0.0;             // meaningful on lane 0 only

    for (int qp = 0; qp < 4; qp++) {
        const int s0 = qp * 256 + 2 * g;
        const int s1 = s0 + 1;

        // wait for fps to publish centroids s0, s1
        wait_progress(b, s1 + 1);

        const float* cen0 = g_newxyz + (size_t)(b * SS + s0) * 3;
        const float* cen1 = g_newxyz + (size_t)(b * SS + s1) * 3;
        const float ax = cen0[0], ay = cen0[1], az = cen0[2];
        const float bx = cen1[0], by = cen1[1], bz = cen1[2];
        const float asq = __fadd_rn(__fadd_rn(__fmul_rn(ax, ax), __fmul_rn(ay, ay)),
                                    __fmul_rn(az, az));
        const float bsq = __fadd_rn(__fadd_rn(__fmul_rn(bx, bx), __fmul_rn(by, by)),
                                    __fmul_rn(bz, bz));
        const ull aX2 = pk2(ax, ax), aY2 = pk2(ay, ay), aZ2 = pk2(az, az);
        const ull aS2 = pk2(asq, asq);
        const ull bX2 = pk2(bx, bx), bY2 = pk2(by, by), bZ2 = pk2(bz, bz);
        const ull bS2 = pk2(bsq, bsq);

        ull key0, key1;
        float kd0, kd1;
        {
            ulonglong2 A = sxy[lane];
            ulonglong2 B = szw[lane];
            ull dot0 = add2(add2(mul2(A.x, aX2), mul2(A.y, aY2)), mul2(B.x, aZ2));
            ull dd0 = add2(add2(mul2(m2two, dot0), aS2), B.y);
            ull dot1 = add2(add2(mul2(A.x, bX2), mul2(A.y, bY2)), mul2(B.x, bZ2));
            ull dd1 = add2(add2(mul2(m2two, dot1), bS2), B.y);
            float de, dq;
            upk2(de, dq, dd0);
            key0 = sort32(makekey(de, 2 * lane), lane);
            key0 = merge32(key0, makekey(dq, 2 * lane + 1), lane);
            kd0 = kth2kd(__shfl_sync(FULLMASK, key0, 31));
            upk2(de, dq, dd1);
            key1 = sort32(makekey(de, 2 * lane), lane);
            key1 = merge32(key1, makekey(dq, 2 * lane + 1), lane);
            kd1 = kth2kd(__shfl_sync(FULLMASK, key1, 31));
        }
        ull buf0 = ~0ull, buf1 = ~0ull;
        int bc0 = 0, bc1 = 0;

        for (int jb = 32; jb < NN / 2; jb += 32) {
            const int j = jb + lane;           // cands 2j, 2j+1
            ulonglong2 A = sxy[j];
            ulonglong2 B = szw[j];
            ull dot0 = add2(add2(mul2(A.x, aX2), mul2(A.y, aY2)), mul2(B.x, aZ2));
            ull dd0 = add2(add2(mul2(m2two, dot0), aS2), B.y);
            ull dot1 = add2(add2(mul2(A.x, bX2), mul2(A.y, bY2)), mul2(B.x, bZ2));
            ull dd1 = add2(add2(mul2(m2two, dot1), bS2), B.y);
            float d0e, d0o, d1e, d1o;
            upk2(d0e, d0o, dd0);
            upk2(d1e, d1o, dd1);
            bool hit = (d0e <= kd0) | (d0o <= kd0) | (d1e <= kd1) | (d1o <= kd1);
            if (__any_sync(FULLMASK, hit)) {
                unsigned m;
                m = __ballot_sync(FULLMASK, d0e <= kd0);
                if (m) push_chunk(makekey(d0e, 2 * j), m, lane, key0, kd0, buf0, bc0);
                m = __ballot_sync(FULLMASK, d0o <= kd0);
                if (m) push_chunk(makekey(d0o, 2 * j + 1), m, lane, key0, kd0, buf0, bc0);
                m = __ballot_sync(FULLMASK, d1e <= kd1);
                if (m) push_chunk(makekey(d1e, 2 * j), m, lane, key1, kd1, buf1, bc1);
                m = __ballot_sync(FULLMASK, d1o <= kd1);
                if (m) push_chunk(makekey(d1o, 2 * j + 1), m, lane, key1, kd1, buf1, bc1);
            }
        }
        if (bc0 > 0) key0 = merge32(key0, buf0, lane);
        if (bc1 > 0) key1 = merge32(key1, buf1, lane);

        // ----- group stats for both queries -----
#pragma unroll
        for (int q = 0; q < 2; q++) {
            ull key = q ? key1 : key0;
            float cx = q ? bx : ax, cy = q ? by : ay, cz = q ? bz : az;
            int sq = q ? s1 : s0;
            int ki = (int)(key & 0x1FFFull);
            ulonglong2 P1 = sxy[ki >> 1];
            ulonglong2 P2 = szw[ki >> 1];
            float xl, xh, yl, yh, zl, zh;
            upk2(xl, xh, P1.x);
            upk2(yl, yh, P1.y);
            upk2(zl, zh, P2.x);
            float px = (ki & 1) ? xh : xl;
            float py = (ki & 1) ? yh : yl;
            float pz = (ki & 1) ? zh : zl;
            float dx = __fsub_rn(px, cx);
            float dy = __fsub_rn(py, cy);
            float dz = __fsub_rn(pz, cz);
            float sdx = dx, sdy = dy, sdz = dz;
            float mdx = dx, mdy = dy, mdz = dz;
            float t1 = dx + dy + dz;
            float t2 = dx * dx + dy * dy + dz * dz;
#pragma unroll
            for (int o = 16; o; o >>= 1) {
                sdx += __shfl_down_sync(FULLMASK, sdx, o);
                sdy += __shfl_down_sync(FULLMASK, sdy, o);
                sdz += __shfl_down_sync(FULLMASK, sdz, o);
                mdx = fmaxf(mdx, __shfl_down_sync(FULLMASK, mdx, o));
                mdy = fmaxf(mdy, __shfl_down_sync(FULLMASK, mdy, o));
                mdz = fmaxf(mdz, __shfl_down_sync(FULLMASK, mdz, o));
                t1 += __shfl_down_sync(FULLMASK, t1, o);
                t2 += __shfl_down_sync(FULLMASK, t2, o);
            }
            if (lane == 0) {
                int ix = (b * SS + sq) * 3;
                g_gsum[ix] = sdx; g_gsum[ix + 1] = sdy; g_gsum[ix + 2] = sdz;
                g_gmax[ix] = mdx; g_gmax[ix + 1] = mdy; g_gmax[ix + 2] = mdz;
                acc1 += (double)t1;
                acc2 += (double)t2;
            }
        }
    }

    if (lane == 0) { s_p1[warp] = acc1; s_p2[warp] = acc2; }
    __syncthreads();
    if (t == 0) {
        double a = 0.0, c = 0.0;
        for (int w = 0; w < 32; w++) { a += s_p1[w]; c += s_p2[w]; }
        atomicAdd(&g_acc[0], a);
        atomicAdd(&g_acc[1], c);
    }
}

// =====================================================================
// K3a: lc build (64 blocks) + BN1 channel sum/sumsq via double atomics.
// =====================================================================
__global__ void __launch_bounds__(256) finalize1_kernel()
{
    const int t = threadIdx.x;
    const int lane = t & 31, warp = t >> 5;
    const int idx = blockIdx.x * 256 + t;     // 0..16383
    __shared__ float s_red[12][8];

    double M = (double)BB * SS * KK * 3;
    double var = (g_acc[1] - g_acc[0] * g_acc[0] / M) / (M - 1.0);  // ddof=1
    const float se = (float)sqrt(var) + 1e-5f;

    int b = idx >> 10, s = idx & (SS - 1);
    const float* gm = g_gmax + idx * 3;
    const float* gs = g_gsum + idx * 3;
    const float* cn = g_newxyz + idx * 3;
    float v[6];
#pragma unroll
    for (int c = 0; c < 3; c++) {
        float mx = __fdiv_rn(gm[c], se);
        float mn = __fdiv_rn(__fdiv_rn(gs[c], 32.0f), se);
        v[c] = __fadd_rn(mx, mn);
        g_lc[(b * 6 + c) * SS + s] = v[c];
    }
#pragma unroll
    for (int c = 0; c < 3; c++) {
        float w = cn[c];
        v[3 + c] = w + w;
        g_lc[(b * 6 + 3 + c) * SS + s] = v[3 + c];
    }

    float sm[12];
#pragma unroll
    for (int c = 0; c < 6; c++) { sm[c] = v[c]; sm[6 + c] = v[c] * v[c]; }
#pragma unroll
    for (int k = 0; k < 12; k++) {
#pragma unroll
        for (int o = 16; o; o >>= 1) sm[k] += __shfl_down_sync(FULLMASK, sm[k], o);
        if (lane == 0) s_red[k][warp] = sm[k];
    }
    __syncthreads();
    if (t < 12) {
        double tot = 0.0;
        for (int w = 0; w < 8; w++) tot += (double)s_red[t][w];
        atomicAdd(&g_ch[t], tot);
    }
}

// =====================================================================
// K3b: cdist with on-the-fly BN1 normalize+relu (16 blocks, one per
// batch); the LAST block to finish also does BN2 + output + resets.
// =====================================================================
__global__ void __launch_bounds__(512) finalize2_kernel(
    const float* __restrict__ bn1g, const float* __restrict__ bn1b,
    const float* __restrict__ bn2g, const float* __restrict__ bn2b,
    float* __restrict__ out)
{
    const int b = blockIdx.x;
    const int t = threadIdx.x, lane = t & 31, warp = t >> 5;
    __shared__ int s_last;
    __shared__ float s_m[36], s_v[36];

    if (t < 6) g_tf[b * 36 + t * 7] = 0.0f;      // diagonal

    if (warp < 15) {
        int i = 0, j = 0, p = warp;
        for (i = 0; i < 5; i++) {
            int row = 5 - i;
            if (p < row) { j = i + 1 + p; break; }
            p -= row;
        }
        const double Ninv = 1.0 / (double)(BB * SS);
        double mid = g_ch[i] * Ninv;
        double vid = g_ch[6 + i] * Ninv - mid * mid;   // biased var
        double mjd = g_ch[j] * Ninv;
        double vjd = g_ch[6 + j] * Ninv - mjd * mjd;
        float mi = (float)mid, di = (float)sqrt(vid + 1e-5);
        float mj = (float)mjd, dj = (float)sqrt(vjd + 1e-5);
        float gi = bn1g[i], bi = bn1b[i];
        float gj = bn1g[j], bj = bn1b[j];

        const float* A  = g_lc + (b * 6 + i) * SS;
        const float* Bp = g_lc + (b * 6 + j) * SS;
        float part = 0.0f;
        for (int s = lane; s < SS; s += 32) {
            float a = fmaxf((A[s] - mi) / di * gi + bi, 0.0f);
            float c = fmaxf((Bp[s] - mj) / dj * gj + bj, 0.0f);
            float d = a - c;
            part += d * d;
        }
#pragma unroll
        for (int o = 16; o; o >>= 1) part += __shfl_down_sync(FULLMASK, part, o);
        if (lane == 0) {
            float v = part > 0.0f ? sqrtf(part) : 0.0f;   // zero-safe
            g_tf[b * 36 + i * 6 + j] = v;
            g_tf[b * 36 + j * 6 + i] = v;
        }
    }

    // ---- completion counter: last block performs BN2 + output + reset ----
    __syncthreads();
    if (t == 0) {
        __threadfence();
        s_last = (atomicAdd(&g_done, 1) == BB - 1) ? 1 : 0;
    }
    __syncthreads();
    if (!s_last) return;
    __threadfence();                              // acquire all g_tf writes

    if (t < 36) {
        float m = 0.0f;
        for (int bb = 0; bb < BB; bb++) m += g_tf[bb * 36 + t];
        m /= (float)BB;
        float v = 0.0f;
        for (int bb = 0; bb < BB; bb++) {
            float d = g_tf[bb * 36 + t] - m;
            v += d * d;
        }
        v /= (float)BB;
        s_m[t] = m; s_v[t] = v;
    }
    __syncthreads();
    for (int i = t; i < BB * 36; i += 512) {
        int f = i % 36;
        float x = g_tf[i];
        float y = (x - s_m[f]) / sqrtf(s_v[f] + 1e-5f) * bn2g[f] + bn2b[f];
        out[i] = fmaxf(y, 0.0f);
    }
    // reset pipeline state for next replay
    if (t >= 64 && t < 64 + BB * 32) g_prog[t - 64] = 0;
    if (t >= 32 && t < 44) g_ch[t - 32] = 0.0;
    if (t == 0) { g_acc[0] = 0.0; g_acc[1] = 0.0; g_done = 0; }
}

// =====================================================================
extern "C" void kernel_launch(void* const* d_in, const int* in_sizes, int n_in,
                              void* d_out, int out_size)
{
    const float* xyz  = (const float*)d_in[0];
    const float* bn1g = (const float*)d_in[1];
    const float* bn1b = (const float*)d_in[2];
    const float* bn2g = (const float*)d_in[3];
    const float* bn2b = (const float*)d_in[4];
    float* out = (float*)d_out;

    // idempotent host-side attribute set (capture-safe)
    cudaFuncSetAttribute(fused_kernel, cudaFuncAttributeMaxDynamicSharedMemorySize,
                         NN * 16);

    fused_kernel<<<BB + BB * 4, 1024, NN * 16>>>(xyz);     // 80 blocks
    finalize1_kernel<<<64, 256>>>();
    finalize2_kernel<<<BB, 512>>>(bn1g, bn1b, bn2g, bn2b, out);
}